// round 16
// baseline (speedup 1.0000x reference)
#include <cuda_runtime.h>
#include <cuda_bf16.h>
#include <cstdint>
#include <cstddef>

#define EMBED 1024
#define HID   4096
#define MTOT  16384          // 4 * 4096 tokens
#define EPSQ  1e-5f
#define WELEMS (HID*EMBED)   // 4194304 (both weights)

// ---------------- scratch (device globals; no allocation allowed) ----------
__device__ __align__(128) double g_partial[2][256];
__device__ __align__(128) float  g_scales[2];                      // s1, s2
__device__ __align__(128) __nv_bfloat16 g_wq1[WELEMS];             // [HID, EMBED]
__device__ __align__(128) __nv_bfloat16 g_wq2[WELEMS];             // [EMBED, HID]
__device__ __align__(128) __nv_bfloat16 g_xq[(size_t)MTOT*EMBED];  // int8 vals as bf16
__device__ __align__(128) float  g_xrecip[MTOT];                   // 1/scale per token
__device__ __align__(128) float  g_h[(size_t)MTOT*HID];            // gelu output fp32
__device__ __align__(128) __nv_bfloat16 g_hq[(size_t)MTOT*HID];
__device__ __align__(128) float  g_hrecip[MTOT];

// ---------------- small PTX helpers ----------------------------------------
__device__ __forceinline__ uint32_t smem_u32(const void* p) {
    return (uint32_t)__cvta_generic_to_shared(p);
}
__device__ __forceinline__ void cp_async16(uint32_t s, const void* g) {
    asm volatile("cp.async.cg.shared.global [%0], [%1], 16;\n" :: "r"(s), "l"(g));
}
__device__ __forceinline__ void cp_commit() {
    asm volatile("cp.async.commit_group;\n");
}
template<int N> __device__ __forceinline__ void cp_wait() {
    asm volatile("cp.async.wait_group %0;\n" :: "n"(N));
}
__device__ __forceinline__ void ldsm4(uint32_t (&r)[4], uint32_t addr) {
    asm volatile("ldmatrix.sync.aligned.m8n8.x4.shared.b16 {%0,%1,%2,%3}, [%4];\n"
        : "=r"(r[0]), "=r"(r[1]), "=r"(r[2]), "=r"(r[3]) : "r"(addr));
}
__device__ __forceinline__ void mma16816(float (&c)[4], const uint32_t (&a)[4],
                                         uint32_t b0, uint32_t b1) {
    asm volatile("mma.sync.aligned.m16n8k16.row.col.f32.bf16.bf16.f32 "
        "{%0,%1,%2,%3}, {%4,%5,%6,%7}, {%8,%9}, {%0,%1,%2,%3};\n"
        : "+f"(c[0]), "+f"(c[1]), "+f"(c[2]), "+f"(c[3])
        : "r"(a[0]), "r"(a[1]), "r"(a[2]), "r"(a[3]), "r"(b0), "r"(b1));
}

// ---------------- weight absmean: deterministic 2-stage reduction ----------
__global__ void k_wabs(const float* __restrict__ w1, const float* __restrict__ w2) {
    const float* w = (blockIdx.y == 0) ? w1 : w2;
    double s = 0.0;
    for (int i = blockIdx.x * 256 + threadIdx.x; i < WELEMS; i += 256 * 256)
        s += (double)fabsf(w[i]);
    __shared__ double sh[256];
    sh[threadIdx.x] = s;
    __syncthreads();
    #pragma unroll
    for (int o = 128; o > 0; o >>= 1) {
        if (threadIdx.x < o) sh[threadIdx.x] += sh[threadIdx.x + o];
        __syncthreads();
    }
    if (threadIdx.x == 0) g_partial[blockIdx.y][blockIdx.x] = sh[0];
}

__global__ void k_wscale() {
    __shared__ double sh[256];
    sh[threadIdx.x] = g_partial[blockIdx.x][threadIdx.x];
    __syncthreads();
    #pragma unroll
    for (int o = 128; o > 0; o >>= 1) {
        if (threadIdx.x < o) sh[threadIdx.x] += sh[threadIdx.x + o];
        __syncthreads();
    }
    if (threadIdx.x == 0)
        g_scales[blockIdx.x] = fmaxf((float)(sh[0] / (double)WELEMS), EPSQ);
}

// ---------------- weight ternary quantization -------------------------------
__global__ void k_quant_w(const float* __restrict__ w1, const float* __restrict__ w2) {
    int i = blockIdx.x * 256 + threadIdx.x;   // grid covers 2*WELEMS exactly
    int sel = (i >= WELEMS);
    int j = sel ? i - WELEMS : i;
    float s = g_scales[sel];
    float v = (sel ? w2 : w1)[j];
    float q = rintf(v / s);                    // round half-to-even, like jnp.round
    q = fmaxf(-1.f, fminf(1.f, q));
    (sel ? g_wq2 : g_wq1)[j] = __float2bfloat16(q);
}

// ---------------- per-token int8 quantization of x (row = 1024) -------------
__global__ void k_quant_x(const float* __restrict__ x) {
    const int r = blockIdx.x;
    const float4* xr = reinterpret_cast<const float4*>(x + (size_t)r * EMBED);
    float4 v = xr[threadIdx.x];
    float m = fmaxf(fmaxf(fabsf(v.x), fabsf(v.y)), fmaxf(fabsf(v.z), fabsf(v.w)));
    #pragma unroll
    for (int o = 16; o; o >>= 1) m = fmaxf(m, __shfl_xor_sync(0xffffffffu, m, o));
    __shared__ float sm[8];
    if ((threadIdx.x & 31) == 0) sm[threadIdx.x >> 5] = m;
    __syncthreads();
    float amax = sm[0];
    #pragma unroll
    for (int i = 1; i < 8; i++) amax = fmaxf(amax, sm[i]);
    const float scale = 127.f / fmaxf(amax, EPSQ);
    float q0 = fmaxf(-128.f, fminf(127.f, rintf(v.x * scale)));
    float q1 = fmaxf(-128.f, fminf(127.f, rintf(v.y * scale)));
    float q2 = fmaxf(-128.f, fminf(127.f, rintf(v.z * scale)));
    float q3 = fmaxf(-128.f, fminf(127.f, rintf(v.w * scale)));
    __nv_bfloat162* o2 = reinterpret_cast<__nv_bfloat162*>(
        g_xq + (size_t)r * EMBED + threadIdx.x * 4);
    o2[0] = __floats2bfloat162_rn(q0, q1);
    o2[1] = __floats2bfloat162_rn(q2, q3);
    if (threadIdx.x == 0) g_xrecip[r] = 1.0f / scale;
}

// ---------------- per-token int8 quantization of h (row = 4096) -------------
__global__ void k_quant_h() {
    const int r = blockIdx.x;
    const float4* hr = reinterpret_cast<const float4*>(g_h + (size_t)r * HID);
    float4 v[4];
    float m = 0.f;
    #pragma unroll
    for (int i = 0; i < 4; i++) {
        v[i] = hr[threadIdx.x + i * 256];
        m = fmaxf(m, fmaxf(fmaxf(fabsf(v[i].x), fabsf(v[i].y)),
                           fmaxf(fabsf(v[i].z), fabsf(v[i].w))));
    }
    #pragma unroll
    for (int o = 16; o; o >>= 1) m = fmaxf(m, __shfl_xor_sync(0xffffffffu, m, o));
    __shared__ float sm[8];
    if ((threadIdx.x & 31) == 0) sm[threadIdx.x >> 5] = m;
    __syncthreads();
    float amax = sm[0];
    #pragma unroll
    for (int i = 1; i < 8; i++) amax = fmaxf(amax, sm[i]);
    const float scale = 127.f / fmaxf(amax, EPSQ);
    #pragma unroll
    for (int i = 0; i < 4; i++) {
        float q0 = fmaxf(-128.f, fminf(127.f, rintf(v[i].x * scale)));
        float q1 = fmaxf(-128.f, fminf(127.f, rintf(v[i].y * scale)));
        float q2 = fmaxf(-128.f, fminf(127.f, rintf(v[i].z * scale)));
        float q3 = fmaxf(-128.f, fminf(127.f, rintf(v[i].w * scale)));
        __nv_bfloat162* o2 = reinterpret_cast<__nv_bfloat162*>(
            g_hq + (size_t)r * HID + (threadIdx.x + i * 256) * 4);
        o2[0] = __floats2bfloat162_rn(q0, q1);
        o2[1] = __floats2bfloat162_rn(q2, q3);
    }
    if (threadIdx.x == 0) g_hrecip[r] = 1.0f / scale;
}

// ---------------- bf16 tensor-core GEMM, CTA tile 128x128x64 ----------------
// A: [M, K] row-major (activations), B: [N, K] row-major (weights, K-major)
// C[m,n] = sum_k A[m,k] * B[n,k]; epilogue scales per row; EPI==0 adds GELU.
// 8 warps (2 x 4), warp tile 64x32, mma m16n8k16 bf16/f32.
// smem: 2 stages x (A 16KB + B 16KB), 128B rows with XOR-16B-chunk swizzle.
template<int EPI, int N, int K>
__global__ __launch_bounds__(256)
void k_gemm(float* __restrict__ Cout) {
    extern __shared__ __align__(128) char smem[];
    const __nv_bfloat16* __restrict__ A = (EPI == 0) ? g_xq  : g_hq;
    const __nv_bfloat16* __restrict__ B = (EPI == 0) ? g_wq1 : g_wq2;
    float* __restrict__ C               = (EPI == 0) ? g_h   : Cout;
    const float* __restrict__ rec       = (EPI == 0) ? g_xrecip : g_hrecip;

    const int tid  = threadIdx.x;
    const int lane = tid & 31;
    const int warp = tid >> 5;
    const int wm = warp >> 2;           // 0..1
    const int wn = warp & 3;            // 0..3
    const int bm = blockIdx.y, bn = blockIdx.x;

    const __nv_bfloat16* Ag = A + (size_t)bm * 128 * K;
    const __nv_bfloat16* Bg = B + (size_t)bn * 128 * K;

    float acc[4][4][4];
    #pragma unroll
    for (int i = 0; i < 4; i++)
        #pragma unroll
        for (int j = 0; j < 4; j++)
            #pragma unroll
            for (int k = 0; k < 4; k++) acc[i][j][k] = 0.f;

    auto load_stage = [&](int s, int k0) {
        char* as = smem + s * 32768;
        char* bs = as + 16384;
        #pragma unroll
        for (int i = 0; i < 4; i++) {
            int idx = tid + i * 256;          // 1024 16B chunks per tile
            int r = idx >> 3, c = idx & 7;    // row 0..127, chunk 0..7
            int off = r * 128 + ((c * 16) ^ ((r & 7) * 16));
            cp_async16(smem_u32(as + off), Ag + (size_t)r * K + k0 + c * 8);
            cp_async16(smem_u32(bs + off), Bg + (size_t)r * K + k0 + c * 8);
        }
        cp_commit();
    };

    load_stage(0, 0);
    constexpr int KT = K / 64;

    // per-lane ldmatrix coordinates (x4 loads)
    const int aRowBase = wm * 64 + (lane & 15);            // lanes 16-31 alias rows 0-15
    const int aColH    = (lane >> 4) * 16;                 // k lo/hi 16B chunk
    const int bRowBase = wn * 32 + (lane & 7) + (lane >> 4) * 8;
    const int bColH    = ((lane >> 3) & 1) * 16;
    const int swz      = (lane & 7) * 16;                  // row%8 chunk XOR

    for (int kt = 0; kt < KT; ++kt) {
        if (kt + 1 < KT) { load_stage((kt + 1) & 1, (kt + 1) * 64); cp_wait<1>(); }
        else             { cp_wait<0>(); }
        __syncthreads();
        char* as = smem + (kt & 1) * 32768;
        char* bs = as + 16384;
        #pragma unroll
        for (int kk = 0; kk < 4; ++kk) {      // four k16 steps per BK=64
            uint32_t a[4][4], b[2][4];
            #pragma unroll
            for (int mi = 0; mi < 4; ++mi) {
                int off = (aRowBase + mi * 16) * 128 + ((kk * 32 + aColH) ^ swz);
                ldsm4(a[mi], smem_u32(as + off));
            }
            #pragma unroll
            for (int nq = 0; nq < 2; ++nq) {
                int off = (bRowBase + nq * 16) * 128 + ((kk * 32 + bColH) ^ swz);
                ldsm4(b[nq], smem_u32(bs + off));
            }
            #pragma unroll
            for (int mi = 0; mi < 4; ++mi)
                #pragma unroll
                for (int nj = 0; nj < 4; ++nj)
                    mma16816(acc[mi][nj], a[mi],
                             b[nj >> 1][(nj & 1) * 2], b[nj >> 1][(nj & 1) * 2 + 1]);
        }
        __syncthreads();
    }

    // epilogue: per-row scale (w_scale * act_recip); EPI==0 applies exact GELU
    const float ws = g_scales[EPI];
    #pragma unroll
    for (int mi = 0; mi < 4; ++mi) {
        const int row0 = bm * 128 + wm * 64 + mi * 16 + (lane >> 2);
        const float f0 = ws * rec[row0];
        const float f1 = ws * rec[row0 + 8];
        #pragma unroll
        for (int nj = 0; nj < 4; ++nj) {
            const int col = bn * 128 + wn * 32 + nj * 8 + (lane & 3) * 2;
            float c0 = acc[mi][nj][0] * f0;
            float c1 = acc[mi][nj][1] * f0;
            float c2 = acc[mi][nj][2] * f1;
            float c3 = acc[mi][nj][3] * f1;
            if (EPI == 0) {                       // exact erf-GELU: x * Phi(x)
                c0 *= normcdff(c0);
                c1 *= normcdff(c1);
                c2 *= normcdff(c2);
                c3 *= normcdff(c3);
            }
            *reinterpret_cast<float2*>(C + (size_t)row0 * N + col)       = make_float2(c0, c1);
            *reinterpret_cast<float2*>(C + (size_t)(row0 + 8) * N + col) = make_float2(c2, c3);
        }
    }
}

// ---------------- launch -----------------------------------------------------
extern "C" void kernel_launch(void* const* d_in, const int* in_sizes, int n_in,
                              void* d_out, int out_size) {
    (void)in_sizes; (void)n_in; (void)out_size;
    const float* x  = (const float*)d_in[0];   // [4,4096,1024]
    const float* w1 = (const float*)d_in[1];   // [4096,1024]
    const float* w2 = (const float*)d_in[2];   // [1024,4096]
    float* out = (float*)d_out;                // [4,4096,1024]

    cudaFuncSetAttribute((const void*)k_gemm<0, HID, EMBED>,
                         cudaFuncAttributeMaxDynamicSharedMemorySize, 65536);
    cudaFuncSetAttribute((const void*)k_gemm<1, EMBED, HID>,
                         cudaFuncAttributeMaxDynamicSharedMemorySize, 65536);

    k_wabs<<<dim3(256, 2), 256>>>(w1, w2);
    k_wscale<<<2, 256>>>();
    k_quant_w<<<(2 * WELEMS) / 256, 256>>>(w1, w2);
    k_quant_x<<<MTOT, 256>>>(x);
    k_gemm<0, HID, EMBED><<<dim3(HID / 128, MTOT / 128), 256, 65536>>>(nullptr);
    k_quant_h<<<MTOT, 256>>>();
    k_gemm<1, EMBED, HID><<<dim3(EMBED / 128, MTOT / 128), 256, 65536>>>(out);
}